// round 8
// baseline (speedup 1.0000x reference)
#include <cuda_runtime.h>
#include <cuda_bf16.h>
#include <stdint.h>

#define N_SP 4096
#define CDIM 64
#define MIDD 8
#define BDIM 4
#define NB 64             // n rows per CTA
#define MB 64             // m per tile
#define NSTEP 32          // each m-group does 32 tiles of 64
#define LOG2E 1.4426950408889634f

// ---- attn smem layout (bytes) ----
#define QS_OFF 0                      // 64 rows x 16B
#define KB_OFF 1024                   // 4 bufs x 64 x 16B
#define VB_OFF 5120                   // 4 bufs x 64c x 144B
#define VSTRB 144
#define SM_TOTAL (5120 + 4 * 64 * VSTRB)   // 41984
// epilogue overlays (loop buffers dead):
#define EP_DSM 0                      // 64 floats
#define EP_RS  512                    // 64 floats
#define EP_OS  4096                   // 64c x 68 floats
#define OSTR 68

typedef unsigned long long ull;

// bf16 scratch (allocation-free rule: __device__ globals)
__device__ __nv_bfloat16 g_qb[BDIM * N_SP * MIDD];   // [b][n][8c], pre-scaled by log2e
__device__ __nv_bfloat16 g_kb[BDIM * N_SP * MIDD];   // [b][m][8c]
__device__ __nv_bfloat16 g_vb[BDIM * CDIM * N_SP];   // [b][c][m]

__device__ __forceinline__ uint32_t smem_u32(const void* p) {
    uint32_t a;
    asm("{ .reg .u64 t; cvta.to.shared.u64 t, %1; cvt.u32.u64 %0, t; }"
        : "=r"(a) : "l"(p));
    return a;
}
__device__ __forceinline__ void ldsm_x4(uint32_t& r0, uint32_t& r1,
                                        uint32_t& r2, uint32_t& r3, uint32_t a) {
    asm volatile("ldmatrix.sync.aligned.m8n8.x4.shared.b16 {%0,%1,%2,%3}, [%4];"
                 : "=r"(r0), "=r"(r1), "=r"(r2), "=r"(r3) : "r"(a));
}
__device__ __forceinline__ void mma_16808(float* d, uint32_t a0, uint32_t a1,
                                          uint32_t b0) {
    asm volatile(
        "mma.sync.aligned.m16n8k8.row.col.f32.bf16.bf16.f32 "
        "{%0,%1,%2,%3}, {%4,%5}, {%6}, {%7,%7,%7,%7};"
        : "=f"(d[0]), "=f"(d[1]), "=f"(d[2]), "=f"(d[3])
        : "r"(a0), "r"(a1), "r"(b0), "f"(0.f));
}
__device__ __forceinline__ void mma_16816(float* d, const uint32_t* a,
                                          uint32_t b0, uint32_t b1) {
    asm volatile(
        "mma.sync.aligned.m16n8k16.row.col.f32.bf16.bf16.f32 "
        "{%0,%1,%2,%3}, {%4,%5,%6,%7}, {%8,%9}, {%0,%1,%2,%3};"
        : "+f"(d[0]), "+f"(d[1]), "+f"(d[2]), "+f"(d[3])
        : "r"(a[0]), "r"(a[1]), "r"(a[2]), "r"(a[3]), "r"(b0), "r"(b1));
}
__device__ __forceinline__ uint32_t pack_bf(float even, float odd) {
    uint32_t r;
    asm("cvt.rn.bf16x2.f32 %0, %1, %2;" : "=r"(r) : "f"(odd), "f"(even));
    return r;
}
__device__ __forceinline__ float ex2(float v) {
    float r;
    asm("ex2.approx.f32 %0, %1;" : "=f"(r) : "f"(v));
    return r;
}
__device__ __forceinline__ ull f2fma(ull a, ull b, ull c) {
    ull d;
    asm("fma.rn.f32x2 %0, %1, %2, %3;" : "=l"(d) : "l"(a), "l"(b), "l"(c));
    return d;
}
__device__ __forceinline__ ull pk2(float x, float y) {
    ull r;
    asm("mov.b64 %0, {%1, %2};" : "=l"(r) : "f"(x), "f"(y));
    return r;
}
__device__ __forceinline__ float2 upk2(ull v) {
    float2 r;
    asm("mov.b64 {%0, %1}, %2;" : "=f"(r.x), "=f"(r.y) : "l"(v));
    return r;
}
__device__ __forceinline__ void cpasync16(uint32_t dst, const void* src) {
    asm volatile("cp.async.ca.shared.global [%0], [%1], 16;" :: "r"(dst), "l"(src));
}
#define CP_COMMIT() asm volatile("cp.async.commit_group;" ::: "memory")

// ---------------------------------------------------------------------------
// Kernel 1: 1x1-conv projections, f32x2 packed over c-pairs.
//   h=0: q (8 outs, pre-scaled by log2e) + v channels 0..31
//   h=1: k (8 outs) + v channels 32..63
// Weights contiguous in c -> natural (c,c+1) pairs via ulonglong2 broadcast LDS.
// ---------------------------------------------------------------------------
__global__ __launch_bounds__(128) void qkv_kernel(
    const float* __restrict__ x,
    const float* __restrict__ Wq, const float* __restrict__ bq,
    const float* __restrict__ Wk, const float* __restrict__ bk,
    const float* __restrict__ Wv, const float* __restrict__ bv)
{
    __shared__ __align__(16) float sWa[MIDD * CDIM];   // Wq*log2e or Wk
    __shared__ __align__(16) float sWv[32 * CDIM];     // my half of Wv
    __shared__ float sba[MIDD], sbv[32];

    int tid = threadIdx.x;
    int h = blockIdx.x & 1;
    int p = (blockIdx.x >> 1) * 128 + tid;
    int b = p >> 12;
    int n = p & (N_SP - 1);

    const float* Wa = h ? Wk : Wq;
    const float* ba = h ? bk : bq;
    float wscale = h ? 1.f : LOG2E;
    for (int i = tid; i < MIDD * CDIM; i += 128) sWa[i] = Wa[i] * wscale;
    for (int i = tid; i < 32 * CDIM; i += 128) sWv[i] = Wv[h * 32 * CDIM + i];
    if (tid < MIDD) sba[tid] = ba[tid] * wscale;
    if (tid < 32) sbv[tid] = bv[h * 32 + tid];
    __syncthreads();

    // load x row-slice and pack into 32 f32x2 pairs
    ull xd[32];
    {
        const float* xp = x + (size_t)(b * CDIM) * N_SP + n;
#pragma unroll
        for (int cp = 0; cp < 32; cp++) {
            float a = xp[(2 * cp) * N_SP];
            float bb = xp[(2 * cp + 1) * N_SP];
            xd[cp] = pk2(a, bb);
        }
    }

    // q or k (8 outputs)
    float aa[MIDD];
#pragma unroll
    for (int o = 0; o < MIDD; o++) {
        ull acc = 0ULL;
        const ulonglong2* wp = reinterpret_cast<const ulonglong2*>(&sWa[o * CDIM]);
#pragma unroll
        for (int i = 0; i < 16; i++) {
            ulonglong2 w = wp[i];
            acc = f2fma(w.x, xd[2 * i], acc);
            acc = f2fma(w.y, xd[2 * i + 1], acc);
        }
        float2 u = upk2(acc);
        aa[o] = u.x + u.y + sba[o];
    }
    {
        uint4 u;
        __nv_bfloat162 t0 = __floats2bfloat162_rn(aa[0], aa[1]);
        __nv_bfloat162 t1 = __floats2bfloat162_rn(aa[2], aa[3]);
        __nv_bfloat162 t2 = __floats2bfloat162_rn(aa[4], aa[5]);
        __nv_bfloat162 t3 = __floats2bfloat162_rn(aa[6], aa[7]);
        u.x = *(uint32_t*)&t0; u.y = *(uint32_t*)&t1;
        u.z = *(uint32_t*)&t2; u.w = *(uint32_t*)&t3;
        __nv_bfloat16* dst = (h ? g_kb : g_qb) + (size_t)(b * N_SP + n) * MIDD;
        *(uint4*)dst = u;
    }

    // v half (32 outputs)
#pragma unroll
    for (int o = 0; o < 32; o++) {
        ull acc = 0ULL;
        const ulonglong2* wp = reinterpret_cast<const ulonglong2*>(&sWv[o * CDIM]);
#pragma unroll
        for (int i = 0; i < 16; i++) {
            ulonglong2 w = wp[i];
            acc = f2fma(w.x, xd[2 * i], acc);
            acc = f2fma(w.y, xd[2 * i + 1], acc);
        }
        float2 u = upk2(acc);
        float v = u.x + u.y + sbv[o];
        g_vb[(size_t)(b * CDIM + h * 32 + o) * N_SP + n] = __float2bfloat16(v);
    }
}

// ---------------------------------------------------------------------------
// Kernel 2: HMMA flash attention, per-K-step interleaved QK->exp->PV so the
// MUFU (exp) and tensor pipes alternate in program order.
// CTA = 128 thr (4 warps), NB=64 n-rows; warp w: m-group mg=w&1, rows (w>>1)*32.
// ---------------------------------------------------------------------------
__global__ __launch_bounds__(128, 2) void attn_kernel(
    const float* __restrict__ x,
    const float* __restrict__ gamma,
    float* __restrict__ out)
{
    __shared__ __align__(16) char smem[SM_TOTAL];
    uint32_t sb = smem_u32(smem);

    int tid = threadIdx.x;
    int w = tid >> 5;
    int t = tid & 31;
    int mg = w & 1;
    int wrow = (w >> 1) * 32;
    int b = blockIdx.x >> 6;
    int n0 = (blockIdx.x & 63) * NB;

    const __nv_bfloat16* vb0 = g_vb + (size_t)b * CDIM * N_SP;
    const __nv_bfloat16* kb0 = g_kb + (size_t)b * N_SP * MIDD;

    // ---- stage Q tile [64 rows][16B] ----
    if (tid < NB) {
        *(uint4*)(smem + QS_OFF + tid * 16) =
            *(const uint4*)(g_qb + (size_t)(b * N_SP + n0 + tid) * MIDD);
    }

    // ---- prologue: tiles 0,1 -> parity-0 buffers ----
    {
#pragma unroll
        for (int i = 0; i < 8; i++) {
            int ch = tid + 128 * i;
            int tile = ch >> 9;
            int c2 = ch & 511;
            int c = c2 >> 3, q8 = c2 & 7;
            cpasync16(sb + VB_OFF + (tile * 2) * (64 * VSTRB) + c * VSTRB + q8 * 16,
                      vb0 + c * N_SP + tile * MB + q8 * 8);
        }
        {
            int tile = tid >> 6, row = tid & 63;
            cpasync16(sb + KB_OFF + (tile * 2) * 1024 + row * 16,
                      kb0 + (tile * MB + row) * MIDD);
        }
        CP_COMMIT();
    }
    __syncthreads();

    // Q A-frags: rows wrow..wrow+31
    uint32_t qa[4];
    ldsm_x4(qa[0], qa[1], qa[2], qa[3], sb + QS_OFF + (wrow + t) * 16);

    float o0[8][4], o1[8][4];
#pragma unroll
    for (int g2 = 0; g2 < 8; g2++)
#pragma unroll
        for (int j = 0; j < 4; j++) { o0[g2][j] = 0.f; o1[g2][j] = 0.f; }
    float d0A = 0.f, d0B = 0.f, d1A = 0.f, d1B = 0.f;

    int crow_base = ((t & 16) >> 1) + (t & 7);
    int col_base = ((t >> 3) & 1) * 8;

    for (int step = 0; step < NSTEP; step++) {
        // issue next pair of tiles
        if (step + 1 < NSTEP) {
            int par = (step + 1) & 1;
            int m0n = 2 * (step + 1) * MB;
#pragma unroll
            for (int i = 0; i < 8; i++) {
                int ch = tid + 128 * i;
                int tile = ch >> 9;
                int c2 = ch & 511;
                int c = c2 >> 3, q8 = c2 & 7;
                cpasync16(sb + VB_OFF + (tile * 2 + par) * (64 * VSTRB) + c * VSTRB + q8 * 16,
                          vb0 + c * N_SP + m0n + tile * MB + q8 * 8);
            }
            {
                int tile = tid >> 6, row = tid & 63;
                cpasync16(sb + KB_OFF + (tile * 2 + par) * 1024 + row * 16,
                          kb0 + (m0n + tile * MB + row) * MIDD);
            }
            CP_COMMIT();
            asm volatile("cp.async.wait_group 1;" ::: "memory");
        } else {
            asm volatile("cp.async.wait_group 0;" ::: "memory");
        }
        __syncthreads();

        int par = step & 1;
        uint32_t kbase = sb + KB_OFF + (mg * 2 + par) * 1024;
        uint32_t vbase = sb + VB_OFF + (mg * 2 + par) * (64 * VSTRB);

#pragma unroll
        for (int kh = 0; kh < 2; kh++) {
            uint32_t kb4[4];
            ldsm_x4(kb4[0], kb4[1], kb4[2], kb4[3], kbase + (kh * 32 + t) * 16);
#pragma unroll
            for (int ks2 = 0; ks2 < 2; ks2++) {
                int ks = kh * 2 + ks2;
                uint32_t p0[4], p1[4];
#pragma unroll
                for (int hf = 0; hf < 2; hf++) {
                    float d0[4], d1[4];
                    mma_16808(d0, qa[0], qa[1], kb4[ks2 * 2 + hf]);
                    mma_16808(d1, qa[2], qa[3], kb4[ks2 * 2 + hf]);
                    float e00 = ex2(d0[0]), e01 = ex2(d0[1]);
                    float e02 = ex2(d0[2]), e03 = ex2(d0[3]);
                    float e10 = ex2(d1[0]), e11 = ex2(d1[1]);
                    float e12 = ex2(d1[2]), e13 = ex2(d1[3]);
                    d0A += e00 + e01; d0B += e02 + e03;
                    d1A += e10 + e11; d1B += e12 + e13;
                    p0[hf * 2]     = pack_bf(e00, e01);
                    p0[hf * 2 + 1] = pack_bf(e02, e03);
                    p1[hf * 2]     = pack_bf(e10, e11);
                    p1[hf * 2 + 1] = pack_bf(e12, e13);
                }
                // PV for this K-step
#pragma unroll
                for (int gp = 0; gp < 4; gp++) {
                    int crow = gp * 16 + crow_base;
                    int col = ks * 16 + col_base;
                    uint32_t r0, r1, r2, r3;
                    ldsm_x4(r0, r1, r2, r3, vbase + crow * VSTRB + col * 2);
                    mma_16816(o0[gp * 2],     p0, r0, r1);
                    mma_16816(o0[gp * 2 + 1], p0, r2, r3);
                    mma_16816(o1[gp * 2],     p1, r0, r1);
                    mma_16816(o1[gp * 2 + 1], p1, r2, r3);
                }
            }
        }
        __syncthreads();
    }

    // ---- denominators: lane-quad reduce, then combine m-groups in smem ----
    d0A += __shfl_xor_sync(~0u, d0A, 1); d0A += __shfl_xor_sync(~0u, d0A, 2);
    d0B += __shfl_xor_sync(~0u, d0B, 1); d0B += __shfl_xor_sync(~0u, d0B, 2);
    d1A += __shfl_xor_sync(~0u, d1A, 1); d1A += __shfl_xor_sync(~0u, d1A, 2);
    d1B += __shfl_xor_sync(~0u, d1B, 1); d1B += __shfl_xor_sync(~0u, d1B, 2);

    float* dsm = (float*)(smem + EP_DSM);
    float* rs  = (float*)(smem + EP_RS);
    float* Os  = (float*)(smem + EP_OS);
    int r0w = wrow + (t >> 2);

    if (mg == 0 && (t & 3) == 0) {
        dsm[r0w] = d0A; dsm[r0w + 8] = d0B;
        dsm[r0w + 16] = d1A; dsm[r0w + 24] = d1B;
    }
    if (mg == 0) {
#pragma unroll
        for (int g2 = 0; g2 < 8; g2++) {
            int c0 = g2 * 8 + 2 * (t & 3);
            int nA = wrow + (t >> 2);
            Os[c0 * OSTR + nA]            = o0[g2][0];
            Os[(c0 + 1) * OSTR + nA]      = o0[g2][1];
            Os[c0 * OSTR + nA + 8]        = o0[g2][2];
            Os[(c0 + 1) * OSTR + nA + 8]  = o0[g2][3];
            Os[c0 * OSTR + nA + 16]       = o1[g2][0];
            Os[(c0 + 1) * OSTR + nA + 16] = o1[g2][1];
            Os[c0 * OSTR + nA + 24]       = o1[g2][2];
            Os[(c0 + 1) * OSTR + nA + 24] = o1[g2][3];
        }
    }
    __syncthreads();
    if (mg == 1) {
        if ((t & 3) == 0) {
            dsm[r0w] += d0A; dsm[r0w + 8] += d0B;
            dsm[r0w + 16] += d1A; dsm[r0w + 24] += d1B;
        }
#pragma unroll
        for (int g2 = 0; g2 < 8; g2++) {
            int c0 = g2 * 8 + 2 * (t & 3);
            int nA = wrow + (t >> 2);
            Os[c0 * OSTR + nA]            += o0[g2][0];
            Os[(c0 + 1) * OSTR + nA]      += o0[g2][1];
            Os[c0 * OSTR + nA + 8]        += o0[g2][2];
            Os[(c0 + 1) * OSTR + nA + 8]  += o0[g2][3];
            Os[c0 * OSTR + nA + 16]       += o1[g2][0];
            Os[(c0 + 1) * OSTR + nA + 16] += o1[g2][1];
            Os[c0 * OSTR + nA + 24]       += o1[g2][2];
            Os[(c0 + 1) * OSTR + nA + 24] += o1[g2][3];
        }
    }
    __syncthreads();
    if (tid < NB) rs[tid] = gamma[0] / dsm[tid];
    __syncthreads();

    // ---- coalesced write: out[c][n] = Os*rs + x ----
#pragma unroll
    for (int rr = 0; rr < 8; rr++) {
        int f = tid + 128 * rr;          // float4 id: 64 c-rows x 16 per row
        int c = f >> 4, j4 = f & 15;
        float4 o = *(float4*)&Os[c * OSTR + j4 * 4];
        float4 rv = *(float4*)&rs[j4 * 4];
        size_t base = (size_t)(b * CDIM + c) * N_SP + n0 + j4 * 4;
        float4 xv = *(const float4*)&x[base];
        o.x = fmaf(o.x, rv.x, xv.x);
        o.y = fmaf(o.y, rv.y, xv.y);
        o.z = fmaf(o.z, rv.z, xv.z);
        o.w = fmaf(o.w, rv.w, xv.w);
        *(float4*)&out[base] = o;
    }
}

// ---------------------------------------------------------------------------
extern "C" void kernel_launch(void* const* d_in, const int* in_sizes, int n_in,
                              void* d_out, int out_size)
{
    const float* x     = (const float*)d_in[0];
    const float* Wq    = (const float*)d_in[1];
    const float* bq    = (const float*)d_in[2];
    const float* Wk    = (const float*)d_in[3];
    const float* bk    = (const float*)d_in[4];
    const float* Wv    = (const float*)d_in[5];
    const float* bv    = (const float*)d_in[6];
    const float* gamma = (const float*)d_in[7];
    float* out = (float*)d_out;

    qkv_kernel<<<256, 128>>>(x, Wq, bq, Wk, bk, Wv, bv);
    attn_kernel<<<BDIM * (N_SP / NB), 128>>>(x, gamma, out);
}